// round 10
// baseline (speedup 1.0000x reference)
#include <cuda_runtime.h>

// CFConv fused: B=4, N=4096, K=30 (pad 32), C=64, E=300
// out[b,n,c] = sum_k gelu( gelu(ef@W1+b1) @ W2 + b2 )[c] * x[b, E_idx[b,n,k], c]
//
// FIX THIS ROUND: E_idx read as INT32 (the harness materializes indices as
// int32 per the stub dtype table; prior round's int64 read fused index pairs,
// giving a garbage gather -> rel_err ~= sqrt(2) signature). Inputs resolved by
// element count (injective). Gather indices masked to [0,4096) (no-op when
// data is valid).
//
// Kernel body unchanged: static __shared__ <= 48 KB, no cudaFuncSetAttribute,
// no inline asm. W1/W2 via LDG (L1-resident). 2 nodes per CTA iteration,
// 128 threads per node, 2k x 8c register tiles.

#define NPAIRS 8192
#define GRIDSZ 296

__device__ __forceinline__ float gelu_f(float v) {
    return 0.5f * v * (1.0f + erff(v * 0.70710678118654752440f));
}

__global__ __launch_bounds__(256, 2)
void cfconv_kernel(const float* __restrict__ x,
                   const float* __restrict__ ef,
                   const int* __restrict__ eidx,
                   const float* __restrict__ W1,
                   const float* __restrict__ b1,
                   const float* __restrict__ W2,
                   const float* __restrict__ b2,
                   float* __restrict__ out)
{
    __shared__ float efs[2][32][100];   // 25600 B, pitch 100 fl (25 float4)
    __shared__ float hs[2][32][68];     // 17408 B, pitch 68 fl
    __shared__ float reds[2][4][64];    //  2048 B
    __shared__ int   idxs[2][32];       //   256 B   (total 45312 B static)

    const int tid = threadIdx.x;
    const int nd  = tid >> 7;           // node within pair (0..1)
    const int l   = tid & 127;
    const int ti  = l >> 3;             // 0..15 -> k = 2ti, 2ti+1
    const int tj  = l & 7;              // cols {4tj..} and {32+4tj..}
    const int wofn = ti >> 2;           // warp index within node (0..3)

    const float4* W14 = (const float4*)W1;
    const float4* W24 = (const float4*)W2;
    const float4* b14 = (const float4*)b1;
    const float4* b24 = (const float4*)b2;

    const float4 c1A = b14[tj],     c1B = b14[8 + tj];
    const float4 c2A = b24[tj],     c2B = b24[8 + tj];

    const float4* efg4 = (const float4*)ef;
    const float4* efs4 = (const float4*)efs;

    for (int p = blockIdx.x; p < NPAIRS; p += gridDim.x) {
        const int nid0 = p << 1;

        if (tid < 64) {
            int n2 = tid >> 5, k = tid & 31;
            // int32 indices; mask keeps gather in-range regardless of data
            idxs[n2][k] = (k < 30)
                ? (eidx[(nid0 + n2) * 30 + k] & 4095) : 0;
        }

        float acc[2][8];
        #pragma unroll
        for (int a_ = 0; a_ < 2; ++a_)
            #pragma unroll
            for (int b_ = 0; b_ < 8; ++b_) acc[a_][b_] = 0.f;

        // ---- GEMM1: h = ef @ W1, E chunked 3 x 100; W1 rows via LDG (L1) ----
        for (int ch = 0; ch < 3; ++ch) {
            __syncthreads();
            #pragma unroll 1
            for (int u = tid; u < 1500; u += 256) {      // 2 nodes x 30 k x 25 f4
                int n2 = u / 750;
                int r  = u - n2 * 750;
                int k  = r / 25;
                int e4 = r - k * 25;
                ((float4*)efs)[(n2 * 32 + k) * 25 + e4] =
                    efg4[(long long)((nid0 + n2) * 30 + k) * 75 + ch * 25 + e4];
            }
            __syncthreads();

            const float4* ea = efs4 + (nd * 32 + 2 * ti) * 25;
            int ew = (ch * 100) * 16 + tj;               // advances 64 per e4
            #pragma unroll 1
            for (int e4 = 0; e4 < 25; ++e4, ew += 64) {
                float4 a0 = ea[e4];
                float4 a1 = ea[e4 + 25];
                float4 w0A = W14[ew],      w0B = W14[ew + 8];
                float4 w1A = W14[ew + 16], w1B = W14[ew + 24];
                float4 w2A = W14[ew + 32], w2B = W14[ew + 40];
                float4 w3A = W14[ew + 48], w3B = W14[ew + 56];
                #pragma unroll
                for (int r2 = 0; r2 < 2; ++r2) {
                    float s0 = r2 ? a1.x : a0.x;
                    float s1 = r2 ? a1.y : a0.y;
                    float s2 = r2 ? a1.z : a0.z;
                    float s3 = r2 ? a1.w : a0.w;
                    acc[r2][0] = fmaf(s0, w0A.x, fmaf(s1, w1A.x, fmaf(s2, w2A.x, fmaf(s3, w3A.x, acc[r2][0]))));
                    acc[r2][1] = fmaf(s0, w0A.y, fmaf(s1, w1A.y, fmaf(s2, w2A.y, fmaf(s3, w3A.y, acc[r2][1]))));
                    acc[r2][2] = fmaf(s0, w0A.z, fmaf(s1, w1A.z, fmaf(s2, w2A.z, fmaf(s3, w3A.z, acc[r2][2]))));
                    acc[r2][3] = fmaf(s0, w0A.w, fmaf(s1, w1A.w, fmaf(s2, w2A.w, fmaf(s3, w3A.w, acc[r2][3]))));
                    acc[r2][4] = fmaf(s0, w0B.x, fmaf(s1, w1B.x, fmaf(s2, w2B.x, fmaf(s3, w3B.x, acc[r2][4]))));
                    acc[r2][5] = fmaf(s0, w0B.y, fmaf(s1, w1B.y, fmaf(s2, w2B.y, fmaf(s3, w3B.y, acc[r2][5]))));
                    acc[r2][6] = fmaf(s0, w0B.z, fmaf(s1, w1B.z, fmaf(s2, w2B.z, fmaf(s3, w3B.z, acc[r2][6]))));
                    acc[r2][7] = fmaf(s0, w0B.w, fmaf(s1, w1B.w, fmaf(s2, w2B.w, fmaf(s3, w3B.w, acc[r2][7]))));
                }
            }
        }

        // ---- bias + exact gelu -> hs ----
        #pragma unroll
        for (int r2 = 0; r2 < 2; ++r2) {
            float* hrow = &hs[nd][2 * ti + r2][0];
            float4 vA = make_float4(gelu_f(acc[r2][0] + c1A.x), gelu_f(acc[r2][1] + c1A.y),
                                    gelu_f(acc[r2][2] + c1A.z), gelu_f(acc[r2][3] + c1A.w));
            float4 vB = make_float4(gelu_f(acc[r2][4] + c1B.x), gelu_f(acc[r2][5] + c1B.y),
                                    gelu_f(acc[r2][6] + c1B.z), gelu_f(acc[r2][7] + c1B.w));
            *(float4*)(hrow + 4 * tj)      = vA;
            *(float4*)(hrow + 32 + 4 * tj) = vB;
        }
        __syncthreads();

        // ---- GEMM2: W = h @ W2 (W2 rows via LDG, L1-hot) ----
        #pragma unroll
        for (int a_ = 0; a_ < 2; ++a_)
            #pragma unroll
            for (int b_ = 0; b_ < 8; ++b_) acc[a_][b_] = 0.f;
        {
            const float* hb = &hs[nd][2 * ti][0];
            #pragma unroll 2
            for (int cp = 0; cp < 64; ++cp) {
                float h0 = hb[cp];
                float h1 = hb[cp + 68];
                float4 wA = W24[cp * 16 + tj];
                float4 wB = W24[cp * 16 + 8 + tj];
                acc[0][0] = fmaf(h0, wA.x, acc[0][0]); acc[0][1] = fmaf(h0, wA.y, acc[0][1]);
                acc[0][2] = fmaf(h0, wA.z, acc[0][2]); acc[0][3] = fmaf(h0, wA.w, acc[0][3]);
                acc[0][4] = fmaf(h0, wB.x, acc[0][4]); acc[0][5] = fmaf(h0, wB.y, acc[0][5]);
                acc[0][6] = fmaf(h0, wB.z, acc[0][6]); acc[0][7] = fmaf(h0, wB.w, acc[0][7]);
                acc[1][0] = fmaf(h1, wA.x, acc[1][0]); acc[1][1] = fmaf(h1, wA.y, acc[1][1]);
                acc[1][2] = fmaf(h1, wA.z, acc[1][2]); acc[1][3] = fmaf(h1, wA.w, acc[1][3]);
                acc[1][4] = fmaf(h1, wB.x, acc[1][4]); acc[1][5] = fmaf(h1, wB.y, acc[1][5]);
                acc[1][6] = fmaf(h1, wB.z, acc[1][6]); acc[1][7] = fmaf(h1, wB.w, acc[1][7]);
            }
        }

        // ---- bias + gelu, gather x rows, per-thread partials ----
        float pA[4] = {0.f, 0.f, 0.f, 0.f};
        float pB[4] = {0.f, 0.f, 0.f, 0.f};
        {
            const int bidx = (nid0 + nd) >> 12;
            const float4* xb = (const float4*)x + (long long)bidx * 4096 * 16;
            #pragma unroll
            for (int r2 = 0; r2 < 2; ++r2) {
                int k = 2 * ti + r2;
                if (k < 30) {
                    int ix = idxs[nd][k];
                    float4 xA = xb[ix * 16 + tj];
                    float4 xB = xb[ix * 16 + 8 + tj];
                    pA[0] += gelu_f(acc[r2][0] + c2A.x) * xA.x;
                    pA[1] += gelu_f(acc[r2][1] + c2A.y) * xA.y;
                    pA[2] += gelu_f(acc[r2][2] + c2A.z) * xA.z;
                    pA[3] += gelu_f(acc[r2][3] + c2A.w) * xA.w;
                    pB[0] += gelu_f(acc[r2][4] + c2B.x) * xB.x;
                    pB[1] += gelu_f(acc[r2][5] + c2B.y) * xB.y;
                    pB[2] += gelu_f(acc[r2][6] + c2B.z) * xB.z;
                    pB[3] += gelu_f(acc[r2][7] + c2B.w) * xB.w;
                }
            }
        }

        // ---- warp butterfly over ti (lane bits 3,4), leaders -> reds ----
        #pragma unroll
        for (int off = 8; off <= 16; off <<= 1) {
            #pragma unroll
            for (int j = 0; j < 4; ++j) {
                pA[j] += __shfl_xor_sync(0xFFFFFFFFu, pA[j], off);
                pB[j] += __shfl_xor_sync(0xFFFFFFFFu, pB[j], off);
            }
        }
        if ((l & 31) < 8) {
            *(float4*)&reds[nd][wofn][4 * tj]      = make_float4(pA[0], pA[1], pA[2], pA[3]);
            *(float4*)&reds[nd][wofn][32 + 4 * tj] = make_float4(pB[0], pB[1], pB[2], pB[3]);
        }
        __syncthreads();

        // ---- sum 4 warp rows -> out ----
        if (tid < 128) {
            int n2 = tid >> 6, c = tid & 63;
            float s = reds[n2][0][c] + reds[n2][1][c] + reds[n2][2][c] + reds[n2][3][c];
            out[(long long)(nid0 + n2) * 64 + c] = s;
        }
        __syncthreads();   // protect smem reuse next iteration
    }
}

extern "C" void kernel_launch(void* const* d_in, const int* in_sizes, int n_in,
                              void* d_out, int out_size) {
    // Resolve inputs by element count (injective for this problem):
    //   ef: 147,456,000   x: 1,048,576   E_idx: 491,520 (int32)
    //   W1: 19,200        W2: 4,096      b1/b2: 64 (both zero vectors)
    const float* x  = 0;
    const float* ef = 0;
    const int*   ei = 0;
    const float* W1 = 0;
    const float* b1 = 0;
    const float* W2 = 0;
    const float* b2 = 0;
    for (int i = 0; i < n_in; ++i) {
        int sz = in_sizes[i];
        if      (sz == 147456000) ef = (const float*)d_in[i];
        else if (sz == 1048576)   x  = (const float*)d_in[i];
        else if (sz == 491520)    ei = (const int*)d_in[i];
        else if (sz == 19200)     W1 = (const float*)d_in[i];
        else if (sz == 4096)      W2 = (const float*)d_in[i];
        else if (sz == 64) { if (!b1) b1 = (const float*)d_in[i]; else b2 = (const float*)d_in[i]; }
    }
    if (!b2) b2 = b1;
    float* out = (float*)d_out;

    cfconv_kernel<<<GRIDSZ, 256>>>(x, ef, ei, W1, b1, W2, b2, out);
}

// round 11
// speedup vs baseline: 1.5223x; 1.5223x over previous
#include <cuda_runtime.h>

// CFConv fused: B=4, N=4096, K=30 (pad 32), C=64, E=300
// out[b,n,c] = sum_k gelu( gelu(ef@W1+b1) @ W2 + b2 )[c] * x[b, E_idx[b,n,k], c]
//
// R11: packed fma.rn.f32x2 (FFMA2, 2x fp32 rate) + 4k x 8c register tiles
// (halves load-per-FMA ratio; R10 profile showed L1 52% / fma 25% => scalar
// FFMA issue + W-load traffic bound). 4 nodes per 256-thr CTA iteration,
// 64 threads per node. Dynamic smem 88.6 KB, 2 CTAs/SM (16 warps).
// Inputs resolved by element count; E_idx is int32, masked to [0,4096).

#define NQUADS 4096
#define GRIDSZ 296

// dynamic smem layout (floats)
#define EFS_OFF  0            // [4][32][100]  12800 fl
#define HS_OFF   12800        // [4][32][68]    8704 fl
#define REDS_OFF 21504        // [4][2][64]      512 fl
#define IDX_OFF  22016        // [4][32] int     128 fl
#define SMEM_FL  22144
#define SMEM_BYTES (SMEM_FL * 4)   // 88576 B

__device__ __forceinline__ unsigned long long pk2(float lo, float hi) {
    unsigned long long r;
    asm("mov.b64 %0, {%1, %2};" : "=l"(r) : "f"(lo), "f"(hi));
    return r;
}
__device__ __forceinline__ unsigned long long dup2(float a) { return pk2(a, a); }
__device__ __forceinline__ void ffma2(unsigned long long& d, unsigned long long a,
                                      unsigned long long b) {
    asm("fma.rn.f32x2 %0, %1, %2, %0;" : "+l"(d) : "l"(a), "l"(b));
}
__device__ __forceinline__ float2 unpk(unsigned long long v) {
    float lo, hi;
    asm("mov.b64 {%0, %1}, %2;" : "=f"(lo), "=f"(hi) : "l"(v));
    return make_float2(lo, hi);
}
__device__ __forceinline__ float gelu_f(float v) {
    return 0.5f * v * (1.0f + erff(v * 0.70710678118654752440f));
}

// acc[4 k][8 c as 4 f32x2] += a[k] * b[8 c]
__device__ __forceinline__ void rank1(unsigned long long (&acc)[4][4],
                                      float a0, float a1, float a2, float a3,
                                      float4 bA, float4 bB) {
    unsigned long long bA01 = pk2(bA.x, bA.y), bA23 = pk2(bA.z, bA.w);
    unsigned long long bB01 = pk2(bB.x, bB.y), bB23 = pk2(bB.z, bB.w);
    unsigned long long aa;
    aa = dup2(a0);
    ffma2(acc[0][0], aa, bA01); ffma2(acc[0][1], aa, bA23);
    ffma2(acc[0][2], aa, bB01); ffma2(acc[0][3], aa, bB23);
    aa = dup2(a1);
    ffma2(acc[1][0], aa, bA01); ffma2(acc[1][1], aa, bA23);
    ffma2(acc[1][2], aa, bB01); ffma2(acc[1][3], aa, bB23);
    aa = dup2(a2);
    ffma2(acc[2][0], aa, bA01); ffma2(acc[2][1], aa, bA23);
    ffma2(acc[2][2], aa, bB01); ffma2(acc[2][3], aa, bB23);
    aa = dup2(a3);
    ffma2(acc[3][0], aa, bA01); ffma2(acc[3][1], aa, bA23);
    ffma2(acc[3][2], aa, bB01); ffma2(acc[3][3], aa, bB23);
}

__global__ __launch_bounds__(256, 2)
void cfconv_kernel(const float* __restrict__ x,
                   const float* __restrict__ ef,
                   const int* __restrict__ eidx,
                   const float* __restrict__ W1,
                   const float* __restrict__ b1,
                   const float* __restrict__ W2,
                   const float* __restrict__ b2,
                   float* __restrict__ out)
{
    extern __shared__ float sm[];
    float* efs  = sm + EFS_OFF;
    float* hs   = sm + HS_OFF;
    float* reds = sm + REDS_OFF;
    int*   idxs = (int*)(sm + IDX_OFF);

    const int tid = threadIdx.x;
    const int g   = tid >> 6;   // node within quad (0..3)
    const int lt  = tid & 63;
    const int ti  = lt >> 3;    // k0 = 4*ti (0..7 -> k 0..31)
    const int tj  = lt & 7;     // cols {4tj..4tj+3} and {32+4tj..}
    const int win = (lt >> 5);  // warp within node (0..1)

    const float4* W14 = (const float4*)W1;
    const float4* W24 = (const float4*)W2;
    const float4 c1A = ((const float4*)b1)[tj], c1B = ((const float4*)b1)[8 + tj];
    const float4 c2A = ((const float4*)b2)[tj], c2B = ((const float4*)b2)[8 + tj];

    const float4* efg4 = (const float4*)ef;
    const float4* efs4 = (const float4*)efs;

    for (int q = blockIdx.x; q < NQUADS; q += gridDim.x) {
        const int nid0 = q << 2;

        if (tid < 128) {
            int nd = tid >> 5, k = tid & 31;
            idxs[nd * 32 + k] = (k < 30)
                ? (eidx[(nid0 + nd) * 30 + k] & 4095) : 0;
        }

        unsigned long long acc[4][4];
        #pragma unroll
        for (int a_ = 0; a_ < 4; ++a_)
            #pragma unroll
            for (int b_ = 0; b_ < 4; ++b_) acc[a_][b_] = 0ULL;

        // ---- GEMM1: h = ef @ W1, E chunked 3 x 100; W1 via LDG (L1-hot) ----
        for (int ch = 0; ch < 3; ++ch) {
            __syncthreads();
            #pragma unroll 1
            for (int u = tid; u < 3000; u += 256) {   // 4 nodes x 30 k x 25 f4
                int nd = u / 750;
                int r  = u - nd * 750;
                int k  = r / 25;
                int e4 = r - k * 25;
                ((float4*)efs)[(nd * 32 + k) * 25 + e4] =
                    efg4[(long long)((nid0 + nd) * 30 + k) * 75 + ch * 25 + e4];
            }
            __syncthreads();

            const float4* ea = efs4 + (g * 32 + 4 * ti) * 25;
            int ew = (ch * 100) * 16 + tj;            // +64 per e4 step
            #pragma unroll 1
            for (int e4 = 0; e4 < 25; ++e4, ew += 64) {
                float4 a0 = ea[e4];
                float4 a1 = ea[e4 + 25];
                float4 a2 = ea[e4 + 50];
                float4 a3 = ea[e4 + 75];
                rank1(acc, a0.x, a1.x, a2.x, a3.x, W14[ew],      W14[ew + 8]);
                rank1(acc, a0.y, a1.y, a2.y, a3.y, W14[ew + 16], W14[ew + 24]);
                rank1(acc, a0.z, a1.z, a2.z, a3.z, W14[ew + 32], W14[ew + 40]);
                rank1(acc, a0.w, a1.w, a2.w, a3.w, W14[ew + 48], W14[ew + 56]);
            }
        }

        // ---- bias + exact gelu -> hs (rows 30,31 garbage but never used) ----
        {
            float* hrow = hs + (g * 32 + 4 * ti) * 68;
            #pragma unroll 1
            for (int ik = 0; ik < 4; ++ik) {
                float2 u0 = unpk(acc[ik][0]);
                float2 u1 = unpk(acc[ik][1]);
                float2 u2 = unpk(acc[ik][2]);
                float2 u3 = unpk(acc[ik][3]);
                float4 vA = make_float4(gelu_f(u0.x + c1A.x), gelu_f(u0.y + c1A.y),
                                        gelu_f(u1.x + c1A.z), gelu_f(u1.y + c1A.w));
                float4 vB = make_float4(gelu_f(u2.x + c1B.x), gelu_f(u2.y + c1B.y),
                                        gelu_f(u3.x + c1B.z), gelu_f(u3.y + c1B.w));
                *(float4*)(hrow + ik * 68 + 4 * tj)      = vA;
                *(float4*)(hrow + ik * 68 + 32 + 4 * tj) = vB;
            }
        }
        __syncthreads();

        // ---- GEMM2: W = h @ W2 (W2 via LDG, L1-hot) ----
        #pragma unroll
        for (int a_ = 0; a_ < 4; ++a_)
            #pragma unroll
            for (int b_ = 0; b_ < 4; ++b_) acc[a_][b_] = 0ULL;
        {
            const float* hb = hs + (g * 32 + 4 * ti) * 68;
            #pragma unroll 2
            for (int cp = 0; cp < 64; ++cp) {
                float h0 = hb[cp];
                float h1 = hb[cp + 68];
                float h2 = hb[cp + 136];
                float h3 = hb[cp + 204];
                rank1(acc, h0, h1, h2, h3, W24[cp * 16 + tj], W24[cp * 16 + 8 + tj]);
            }
        }

        // ---- bias + gelu, gather x rows, per-thread partials over 4 k ----
        float pA[4] = {0.f, 0.f, 0.f, 0.f};
        float pB[4] = {0.f, 0.f, 0.f, 0.f};
        {
            const int bidx = nid0 >> 12;   // quads never straddle batch
            const float4* xb = (const float4*)x + (long long)bidx * 4096 * 16;
            #pragma unroll 1
            for (int ik = 0; ik < 4; ++ik) {
                int k = 4 * ti + ik;
                if (k < 30) {
                    float2 u0 = unpk(acc[ik][0]);
                    float2 u1 = unpk(acc[ik][1]);
                    float2 u2 = unpk(acc[ik][2]);
                    float2 u3 = unpk(acc[ik][3]);
                    int ix = idxs[g * 32 + k];
                    float4 xA = xb[ix * 16 + tj];
                    float4 xB = xb[ix * 16 + 8 + tj];
                    pA[0] += gelu_f(u0.x + c2A.x) * xA.x;
                    pA[1] += gelu_f(u0.y + c2A.y) * xA.y;
                    pA[2] += gelu_f(u1.x + c2A.z) * xA.z;
                    pA[3] += gelu_f(u1.y + c2A.w) * xA.w;
                    pB[0] += gelu_f(u2.x + c2B.x) * xB.x;
                    pB[1] += gelu_f(u2.y + c2B.y) * xB.y;
                    pB[2] += gelu_f(u3.x + c2B.z) * xB.z;
                    pB[3] += gelu_f(u3.y + c2B.w) * xB.w;
                }
            }
        }

        // ---- warp butterfly over ti (lane bits 3,4) -> 2 partials/node ----
        #pragma unroll
        for (int off = 8; off <= 16; off <<= 1) {
            #pragma unroll
            for (int j = 0; j < 4; ++j) {
                pA[j] += __shfl_xor_sync(0xFFFFFFFFu, pA[j], off);
                pB[j] += __shfl_xor_sync(0xFFFFFFFFu, pB[j], off);
            }
        }
        if ((lt & 31) < 8) {
            float* rrow = reds + (g * 2 + win) * 64;
            *(float4*)(rrow + 4 * tj)      = make_float4(pA[0], pA[1], pA[2], pA[3]);
            *(float4*)(rrow + 32 + 4 * tj) = make_float4(pB[0], pB[1], pB[2], pB[3]);
        }
        __syncthreads();

        // ---- sum 2 partial rows -> out (256 threads = 4 nodes x 64 cols) ----
        {
            int n2 = tid >> 6, c = tid & 63;
            float s = reds[(n2 * 2) * 64 + c] + reds[(n2 * 2 + 1) * 64 + c];
            out[(long long)(nid0 + n2) * 64 + c] = s;
        }
        __syncthreads();   // protect smem reuse next iteration
    }
}

extern "C" void kernel_launch(void* const* d_in, const int* in_sizes, int n_in,
                              void* d_out, int out_size) {
    // Resolve inputs by element count (injective for this problem):
    //   ef: 147,456,000   x: 1,048,576   E_idx: 491,520 (int32)
    //   W1: 19,200        W2: 4,096      b1/b2: 64 (both zero vectors)
    const float* x  = 0;
    const float* ef = 0;
    const int*   ei = 0;
    const float* W1 = 0;
    const float* b1 = 0;
    const float* W2 = 0;
    const float* b2 = 0;
    for (int i = 0; i < n_in; ++i) {
        int sz = in_sizes[i];
        if      (sz == 147456000) ef = (const float*)d_in[i];
        else if (sz == 1048576)   x  = (const float*)d_in[i];
        else if (sz == 491520)    ei = (const int*)d_in[i];
        else if (sz == 19200)     W1 = (const float*)d_in[i];
        else if (sz == 4096)      W2 = (const float*)d_in[i];
        else if (sz == 64) { if (!b1) b1 = (const float*)d_in[i]; else b2 = (const float*)d_in[i]; }
    }
    if (!b2) b2 = b1;
    float* out = (float*)d_out;

    cudaFuncSetAttribute(cfconv_kernel,
                         cudaFuncAttributeMaxDynamicSharedMemorySize, SMEM_BYTES);
    cfconv_kernel<<<GRIDSZ, 256, SMEM_BYTES>>>(x, ef, ei, W1, b1, W2, b2, out);
}

// round 12
// speedup vs baseline: 1.9314x; 1.2687x over previous
#include <cuda_runtime.h>
#include <cstdint>

// CFConv fused: B=4, N=4096, K=30 (pad 32), C=64, E=300
// out[b,n,c] = sum_k gelu( gelu(ef@W1+b1) @ W2 + b2 )[c] * x[b, E_idx[b,n,k], c]
//
// R12: W1+W2 staged in smem (LDS replaces the redundant per-warp W LDGs that
// pinned L1 at 50%), ef staged via cp.async double-buffer (E chunked 5x60) so
// the DRAM stream overlaps compute. 1 CTA/SM (192 KB smem), 256 thr = 4 nodes
// per iteration, 4k x 8c register tiles, all GEMM FMAs as fma.rn.f32x2.

#define NQUADS 4096
#define GRIDSZ 148

// smem layout (floats)
#define W1_OFF   0          // [300][64]            19200
#define W2_OFF   19200      // [64][64]              4096
#define EFS_OFF  23296      // 2 bufs x [4][32][60] 15360 (pitch 15 f4)
#define HS_OFF   38656      // [4][32][68]           8704
#define REDS_OFF 47360      // [8][64]                512
#define IDX_OFF  47872      // [4][32] int            128
#define SMEM_FL  48000
#define SMEM_BYTES (SMEM_FL * 4)   // 192000 B

__device__ __forceinline__ unsigned long long pk2(float lo, float hi) {
    unsigned long long r;
    asm("mov.b64 %0, {%1, %2};" : "=l"(r) : "f"(lo), "f"(hi));
    return r;
}
__device__ __forceinline__ unsigned long long dup2(float a) { return pk2(a, a); }
__device__ __forceinline__ void ffma2(unsigned long long& d, unsigned long long a,
                                      unsigned long long b) {
    asm("fma.rn.f32x2 %0, %1, %2, %0;" : "+l"(d) : "l"(a), "l"(b));
}
__device__ __forceinline__ float2 unpk(unsigned long long v) {
    float lo, hi;
    asm("mov.b64 {%0, %1}, %2;" : "=f"(lo), "=f"(hi) : "l"(v));
    return make_float2(lo, hi);
}
__device__ __forceinline__ float gelu_f(float v) {
    return 0.5f * v * (1.0f + erff(v * 0.70710678118654752440f));
}
__device__ __forceinline__ void cp16(uint32_t dst, const void* src) {
    asm volatile("cp.async.cg.shared.global [%0], [%1], 16;" :: "r"(dst), "l"(src));
}
#define CP_COMMIT() asm volatile("cp.async.commit_group;" ::: "memory")
#define CP_WAIT0()  asm volatile("cp.async.wait_group 0;" ::: "memory")

// acc[4 k][8 c as 4 f32x2] += a[k] * b[8 c]
__device__ __forceinline__ void rank1(unsigned long long (&acc)[4][4],
                                      float a0, float a1, float a2, float a3,
                                      float4 bA, float4 bB) {
    unsigned long long bA01 = pk2(bA.x, bA.y), bA23 = pk2(bA.z, bA.w);
    unsigned long long bB01 = pk2(bB.x, bB.y), bB23 = pk2(bB.z, bB.w);
    unsigned long long aa;
    aa = dup2(a0);
    ffma2(acc[0][0], aa, bA01); ffma2(acc[0][1], aa, bA23);
    ffma2(acc[0][2], aa, bB01); ffma2(acc[0][3], aa, bB23);
    aa = dup2(a1);
    ffma2(acc[1][0], aa, bA01); ffma2(acc[1][1], aa, bA23);
    ffma2(acc[1][2], aa, bB01); ffma2(acc[1][3], aa, bB23);
    aa = dup2(a2);
    ffma2(acc[2][0], aa, bA01); ffma2(acc[2][1], aa, bA23);
    ffma2(acc[2][2], aa, bB01); ffma2(acc[2][3], aa, bB23);
    aa = dup2(a3);
    ffma2(acc[3][0], aa, bA01); ffma2(acc[3][1], aa, bA23);
    ffma2(acc[3][2], aa, bB01); ffma2(acc[3][3], aa, bB23);
}

__global__ __launch_bounds__(256, 1)
void cfconv_kernel(const float* __restrict__ x,
                   const float* __restrict__ ef,
                   const int* __restrict__ eidx,
                   const float* __restrict__ W1,
                   const float* __restrict__ b1,
                   const float* __restrict__ W2,
                   const float* __restrict__ b2,
                   float* __restrict__ out)
{
    extern __shared__ float sm[];
    float* w1s  = sm + W1_OFF;
    float* w2s  = sm + W2_OFF;
    float* hs   = sm + HS_OFF;
    float* reds = sm + REDS_OFF;
    int*   idxs = (int*)(sm + IDX_OFF);
    const uint32_t efs_s32 =
        (uint32_t)__cvta_generic_to_shared(sm + EFS_OFF);

    const int tid = threadIdx.x;
    const int g   = tid >> 6;   // node within quad (0..3)
    const int lt  = tid & 63;
    const int ti  = lt >> 3;    // k0 = 4*ti
    const int tj  = lt & 7;     // cols {4tj..}, {32+4tj..}
    const int win = lt >> 5;    // warp within node (0..1)

    // stage W1/W2 once per CTA
    {
        float4* w1d = (float4*)w1s;
        const float4* W14g = (const float4*)W1;
        for (int u = tid; u < 4800; u += 256) w1d[u] = W14g[u];
        float4* w2d = (float4*)w2s;
        const float4* W24g = (const float4*)W2;
        for (int u = tid; u < 1024; u += 256) w2d[u] = W24g[u];
    }

    const float4 c1A = ((const float4*)b1)[tj], c1B = ((const float4*)b1)[8 + tj];
    const float4 c2A = ((const float4*)b2)[tj], c2B = ((const float4*)b2)[8 + tj];

    const float4* w14s = (const float4*)w1s;
    const float4* w24s = (const float4*)w2s;
    const float4* efs4 = (const float4*)(sm + EFS_OFF);

    for (int q = blockIdx.x; q < NQUADS; q += gridDim.x) {
        const int nid0 = q << 2;

        if (tid < 128) {
            int nd = tid >> 5, k = tid & 31;
            idxs[nd * 32 + k] = (k < 30)
                ? (eidx[(nid0 + nd) * 30 + k] & 4095) : 0;
        }

        // prefetch chunk 0 -> buf 0  (1800 f4 = 4 nodes x 30 k x 15 f4)
        #pragma unroll 1
        for (int u = tid; u < 1800; u += 256) {
            int nd = u / 450;
            int r  = u - nd * 450;
            int k  = r / 15;
            int e4 = r - k * 15;
            uint32_t dst = efs_s32 + (uint32_t)(((nd * 32 + k) * 15 + e4) << 4);
            cp16(dst, ef + (long long)((nid0 + nd) * 30 + k) * 300 + e4 * 4);
        }
        CP_COMMIT();

        unsigned long long acc[4][4];
        #pragma unroll
        for (int a_ = 0; a_ < 4; ++a_)
            #pragma unroll
            for (int b_ = 0; b_ < 4; ++b_) acc[a_][b_] = 0ULL;

        // ---- GEMM1: E chunked 5 x 60, double-buffered cp.async ----
        #pragma unroll 1
        for (int ch = 0; ch < 5; ++ch) {
            CP_WAIT0();
            __syncthreads();   // buf[ch&1] full; prior reads of other buf done
            if (ch < 4) {
                int buf = (ch + 1) & 1;
                #pragma unroll 1
                for (int u = tid; u < 1800; u += 256) {
                    int nd = u / 450;
                    int r  = u - nd * 450;
                    int k  = r / 15;
                    int e4 = r - k * 15;
                    uint32_t dst = efs_s32 +
                        (uint32_t)((buf * 1920 + (nd * 32 + k) * 15 + e4) << 4);
                    cp16(dst, ef + (long long)((nid0 + nd) * 30 + k) * 300
                                 + (ch + 1) * 60 + e4 * 4);
                }
                CP_COMMIT();
            }

            const float4* ea = efs4 + (ch & 1) * 1920 + (g * 32 + 4 * ti) * 15;
            int ew = (ch * 60) * 16 + tj;        // +64 per e4 step
            #pragma unroll 1
            for (int e4 = 0; e4 < 15; ++e4, ew += 64) {
                float4 a0 = ea[e4];
                float4 a1 = ea[e4 + 15];
                float4 a2 = ea[e4 + 30];
                float4 a3 = ea[e4 + 45];
                rank1(acc, a0.x, a1.x, a2.x, a3.x, w14s[ew],      w14s[ew + 8]);
                rank1(acc, a0.y, a1.y, a2.y, a3.y, w14s[ew + 16], w14s[ew + 24]);
                rank1(acc, a0.z, a1.z, a2.z, a3.z, w14s[ew + 32], w14s[ew + 40]);
                rank1(acc, a0.w, a1.w, a2.w, a3.w, w14s[ew + 48], w14s[ew + 56]);
            }
        }

        // ---- bias + exact gelu -> hs ----
        {
            float* hrow = hs + (g * 32 + 4 * ti) * 68;
            #pragma unroll 1
            for (int ik = 0; ik < 4; ++ik) {
                float2 u0 = unpk(acc[ik][0]);
                float2 u1 = unpk(acc[ik][1]);
                float2 u2 = unpk(acc[ik][2]);
                float2 u3 = unpk(acc[ik][3]);
                float4 vA = make_float4(gelu_f(u0.x + c1A.x), gelu_f(u0.y + c1A.y),
                                        gelu_f(u1.x + c1A.z), gelu_f(u1.y + c1A.w));
                float4 vB = make_float4(gelu_f(u2.x + c1B.x), gelu_f(u2.y + c1B.y),
                                        gelu_f(u3.x + c1B.z), gelu_f(u3.y + c1B.w));
                *(float4*)(hrow + ik * 68 + 4 * tj)      = vA;
                *(float4*)(hrow + ik * 68 + 32 + 4 * tj) = vB;
            }
        }
        __syncthreads();

        // ---- GEMM2: W = h @ W2 (both smem) ----
        #pragma unroll
        for (int a_ = 0; a_ < 4; ++a_)
            #pragma unroll
            for (int b_ = 0; b_ < 4; ++b_) acc[a_][b_] = 0ULL;
        {
            const float* hb = hs + (g * 32 + 4 * ti) * 68;
            #pragma unroll 2
            for (int cp = 0; cp < 64; ++cp) {
                float h0 = hb[cp];
                float h1 = hb[cp + 68];
                float h2 = hb[cp + 136];
                float h3 = hb[cp + 204];
                rank1(acc, h0, h1, h2, h3, w24s[cp * 16 + tj], w24s[cp * 16 + 8 + tj]);
            }
        }

        // ---- bias + gelu, gather x rows, per-thread partials over 4 k ----
        float pA[4] = {0.f, 0.f, 0.f, 0.f};
        float pB[4] = {0.f, 0.f, 0.f, 0.f};
        {
            const int bidx = nid0 >> 12;   // quads never straddle batch
            const float4* xb = (const float4*)x + (long long)bidx * 4096 * 16;
            #pragma unroll 1
            for (int ik = 0; ik < 4; ++ik) {
                int k = 4 * ti + ik;
                if (k < 30) {
                    float2 u0 = unpk(acc[ik][0]);
                    float2 u1 = unpk(acc[ik][1]);
                    float2 u2 = unpk(acc[ik][2]);
                    float2 u3 = unpk(acc[ik][3]);
                    int ix = idxs[g * 32 + k];
                    float4 xA = xb[ix * 16 + tj];
                    float4 xB = xb[ix * 16 + 8 + tj];
                    pA[0] += gelu_f(u0.x + c2A.x) * xA.x;
                    pA[1] += gelu_f(u0.y + c2A.y) * xA.y;
                    pA[2] += gelu_f(u1.x + c2A.z) * xA.z;
                    pA[3] += gelu_f(u1.y + c2A.w) * xA.w;
                    pB[0] += gelu_f(u2.x + c2B.x) * xB.x;
                    pB[1] += gelu_f(u2.y + c2B.y) * xB.y;
                    pB[2] += gelu_f(u3.x + c2B.z) * xB.z;
                    pB[3] += gelu_f(u3.y + c2B.w) * xB.w;
                }
            }
        }

        // ---- warp butterfly over ti (lane bits 3,4) -> 2 partials/node ----
        #pragma unroll
        for (int off = 8; off <= 16; off <<= 1) {
            #pragma unroll
            for (int j = 0; j < 4; ++j) {
                pA[j] += __shfl_xor_sync(0xFFFFFFFFu, pA[j], off);
                pB[j] += __shfl_xor_sync(0xFFFFFFFFu, pB[j], off);
            }
        }
        if ((lt & 31) < 8) {
            float* rrow = reds + (g * 2 + win) * 64;
            *(float4*)(rrow + 4 * tj)      = make_float4(pA[0], pA[1], pA[2], pA[3]);
            *(float4*)(rrow + 32 + 4 * tj) = make_float4(pB[0], pB[1], pB[2], pB[3]);
        }
        __syncthreads();

        // ---- sum 2 partial rows -> out ----
        {
            int n2 = tid >> 6, c = tid & 63;
            float s = reds[(n2 * 2) * 64 + c] + reds[(n2 * 2 + 1) * 64 + c];
            out[(long long)(nid0 + n2) * 64 + c] = s;
        }
        __syncthreads();   // protect smem reuse next iteration
    }
}

extern "C" void kernel_launch(void* const* d_in, const int* in_sizes, int n_in,
                              void* d_out, int out_size) {
    // Resolve inputs by element count (injective for this problem):
    //   ef: 147,456,000   x: 1,048,576   E_idx: 491,520 (int32)
    //   W1: 19,200        W2: 4,096      b1/b2: 64 (both zero vectors)
    const float* x  = 0;
    const float* ef = 0;
    const int*   ei = 0;
    const float* W1 = 0;
    const float* b1 = 0;
    const float* W2 = 0;
    const float* b2 = 0;
    for (int i = 0; i < n_in; ++i) {
        int sz = in_sizes[i];
        if      (sz == 147456000) ef = (const float*)d_in[i];
        else if (sz == 1048576)   x  = (const float*)d_in[i];
        else if (sz == 491520)    ei = (const int*)d_in[i];
        else if (sz == 19200)     W1 = (const float*)d_in[i];
        else if (sz == 4096)      W2 = (const float*)d_in[i];
        else if (sz == 64) { if (!b1) b1 = (const float*)d_in[i]; else b2 = (const float*)d_in[i]; }
    }
    if (!b2) b2 = b1;
    float* out = (float*)d_out;

    cudaFuncSetAttribute(cfconv_kernel,
                         cudaFuncAttributeMaxDynamicSharedMemorySize, SMEM_BYTES);
    cfconv_kernel<<<GRIDSZ, 256, SMEM_BYTES>>>(x, ef, ei, W1, b1, W2, b2, out);
}